// round 10
// baseline (speedup 1.0000x reference)
#include <cuda_runtime.h>
#include <cstdint>

#define NSTEP 128
#define BATCH 8192
#define BC    32
#define NT    128
#define HLD   132            // hcat row stride in 32-bit words (bf16x2), conflict-free
#define WLD   132            // wB1 row stride in words
#define HBUF  (BC*HLD)       // one hcat buffer, words

// ---- SMEM byte offsets ----
#define HCAT_OFF  0                          // 2 buffers x 32 rows x HLD words: [h0|h1|pad]
#define WB1_OFF   (HCAT_OFF + 2*HBUF*4)      // 128 rows x WLD words: [W_ih1(64w) | W_hh1(64w)]
#define SCTAB_OFF (WB1_OFF + 128*WLD*4)      // 3*128 floats (layer0 bias + one-hot select)
#define SB1V_OFF  (SCTAB_OFF + 1536)         // 128 floats
#define SWD_OFF   (SB1V_OFF + 512)           // 2*128 floats
#define SBIT_OFF  (SWD_OFF + 1024)           // 32 ints
#define SPART_OFF (SBIT_OFF + 128)           // 4 warps x 2 x 32 floats
#define SMEM_BYTES (SPART_OFF + 4*64*4)      // ~107KB -> 2 CTAs/SM

__device__ __forceinline__ uint32_t pk_bf(float even, float odd) {
    uint32_t r; asm("cvt.rn.bf16x2.f32 %0, %1, %2;" : "=r"(r) : "f"(odd), "f"(even));
    return r;
}
__device__ __forceinline__ float tanh_fast(float x) {
    float y; asm("tanh.approx.f32 %0, %1;" : "=f"(y) : "f"(x)); return y;
}
__device__ __forceinline__ uint32_t smem_u32(const void* p) {
    uint32_t a;
    asm("{ .reg .u64 t; cvta.to.shared.u64 t, %1; cvt.u32.u64 %0, t; }" : "=r"(a) : "l"(p));
    return a;
}
__device__ __forceinline__ void ldmA(uint32_t* a, uint32_t addr) {
    asm volatile("ldmatrix.sync.aligned.m8n8.x4.shared.b16 {%0,%1,%2,%3}, [%4];"
                 : "=r"(a[0]), "=r"(a[1]), "=r"(a[2]), "=r"(a[3]) : "r"(addr));
}
__device__ __forceinline__ void ldmB(uint32_t* b, uint32_t addr) {
    asm volatile("ldmatrix.sync.aligned.m8n8.x4.shared.b16 {%0,%1,%2,%3}, [%4];"
                 : "=r"(b[0]), "=r"(b[1]), "=r"(b[2]), "=r"(b[3]) : "r"(addr));
}
__device__ __forceinline__ void mma16(float* d, const uint32_t* a, const uint32_t* b) {
    asm volatile("mma.sync.aligned.m16n8k16.row.col.f32.bf16.bf16.f32 "
                 "{%0,%1,%2,%3}, {%4,%5,%6,%7}, {%8,%9}, {%0,%1,%2,%3};"
                 : "+f"(d[0]), "+f"(d[1]), "+f"(d[2]), "+f"(d[3])
                 : "r"(a[0]), "r"(a[1]), "r"(a[2]), "r"(a[3]), "r"(b[0]), "r"(b[1]));
}
#define BAR_SYNC(id)   asm volatile("bar.sync %0, %1;"   :: "n"(id), "n"(NT) : "memory")
#define BAR_ARRIVE(id) asm volatile("bar.arrive %0, %1;" :: "n"(id), "n"(NT) : "memory")

__global__ void __launch_bounds__(NT, 2)
rnn_bf16f_kernel(const float* __restrict__ samples,
                 const float* __restrict__ W_ih0, const float* __restrict__ b_ih0,
                 const float* __restrict__ W_hh0, const float* __restrict__ b_hh0,
                 const float* __restrict__ W_ih1, const float* __restrict__ b_ih1,
                 const float* __restrict__ W_hh1, const float* __restrict__ b_hh1,
                 const float* __restrict__ W_dense, const float* __restrict__ b_dense,
                 float* __restrict__ out)
{
    extern __shared__ char smem[];
    uint32_t* hcat  = (uint32_t*)(smem + HCAT_OFF);
    uint32_t* wB1   = (uint32_t*)(smem + WB1_OFF);
    float*    scTab = (float*)(smem + SCTAB_OFF);
    float*    sB1v  = (float*)(smem + SB1V_OFF);
    float*    sWd   = (float*)(smem + SWD_OFF);
    int*      sBit  = (int*)(smem + SBIT_OFF);
    float*    sPart = (float*)(smem + SPART_OFF);

    const int tid = threadIdx.x;
    const int w   = tid >> 5;         // 0..3, owns 32 n-cols
    const int lane = tid & 31;
    const int g  = lane >> 2;
    const int tq = lane & 3;
    const int gRow = blockIdx.x * BC + tid;   // valid for tid < 32

    // ---- resident W_hh0 B-fragments (bf16): 4 n8-tiles x 8 k-tiles ----
    uint32_t w0[4][8][2];
#pragma unroll
    for (int nt = 0; nt < 4; ++nt) {
        const int j = 32 * w + nt * 8 + g;
#pragma unroll
        for (int kt = 0; kt < 8; ++kt) {
            const float* p = W_hh0 + j * 128 + kt * 16;
            w0[nt][kt][0] = pk_bf(p[2 * tq],     p[2 * tq + 1]);
            w0[nt][kt][1] = pk_bf(p[8 + 2 * tq], p[8 + 2 * tq + 1]);
        }
    }

    // ---- SMEM weight/bias tables ----
    for (int idx = tid; idx < 128 * 64; idx += NT) {
        const int j = idx >> 6, kw = idx & 63;
        wB1[j * WLD + kw]      = pk_bf(W_ih1[j * 128 + 2 * kw], W_ih1[j * 128 + 2 * kw + 1]);
        wB1[j * WLD + 64 + kw] = pk_bf(W_hh1[j * 128 + 2 * kw], W_hh1[j * 128 + 2 * kw + 1]);
    }
    if (tid < 128) {
        const int j = tid;
        float bb = b_ih0[j] + b_hh0[j];
        scTab[j]       = bb + W_ih0[2 * j];
        scTab[128 + j] = bb + W_ih0[2 * j + 1];
        scTab[256 + j] = bb;
        sB1v[j] = b_ih1[j] + b_hh1[j];
        sWd[j]       = W_dense[j];
        sWd[128 + j] = W_dense[128 + j];
    }
    for (int idx = tid; idx < HBUF; idx += NT) hcat[idx] = 0u;   // buffer 0 zeroed
    if (tid < BC) sBit[tid] = 2;
    __syncthreads();

    // ldmatrix per-lane A address base (buffer 0)
    const uint32_t hb0 = smem_u32(hcat)
        + (uint32_t)(((lane & 7) + ((lane >> 3) & 1) * 8) * HLD) * 4u
        + (uint32_t)(((lane >> 4) & 1) * 16);

    // ldmatrix.x4 B lane addressing: tiles (nt=2q+ (lane>>4), half=(lane>>3)&1, row=lane&7)
    // -> regs r0=b[2q][0], r1=b[2q][1], r2=b[2q+1][0], r3=b[2q+1][1]
    uint32_t bAddr[2][2];   // [q][section: 0=W_ih1, 1=W_hh1]
    {
        const uint32_t wbb = smem_u32(wB1);
        const int ntq = (lane >> 4) & 1;
        const int bh  = (lane >> 3) & 1;
        const int br  = lane & 7;
#pragma unroll
        for (int q = 0; q < 2; ++q) {
            const int row = 32 * w + 8 * (2 * q + ntq) + br;
            bAddr[q][0] = wbb + (uint32_t)(row * WLD + 4 * bh) * 4u;
            bAddr[q][1] = bAddr[q][0] + 64u * 4u;
        }
    }
    const float bd0 = b_dense[0], bd1 = b_dense[1];
    float lp = 0.f;

    for (int t = 0; t < NSTEP; ++t) {
        const uint32_t rdoff = (uint32_t)(t & 1) * (HBUF * 4);
        const uint32_t wroff = (uint32_t)((t & 1) ^ 1) * (HBUF * 4);
        uint32_t* hcwm = hcat + ((t & 1) ^ 1) * HBUF;   // write buffer

        float s1 = 0.f;
        if (tid < BC) s1 = __ldg(&samples[(t * BATCH + gRow) * 2 + 1]);

        // ========== L0: acc0 = h0[rd] @ W_hh0^T (K=128, resident B) ==========
        float acc0[2][4][4];
#pragma unroll
        for (int mt = 0; mt < 2; ++mt)
#pragma unroll
            for (int nt = 0; nt < 4; ++nt)
#pragma unroll
                for (int i = 0; i < 4; ++i) acc0[mt][nt][i] = 0.f;

#pragma unroll
        for (int kt = 0; kt < 8; ++kt) {
#pragma unroll
            for (int mt = 0; mt < 2; ++mt) {
                uint32_t a[4];
                ldmA(a, hb0 + rdoff + (uint32_t)(mt * 16 * HLD * 4) + (uint32_t)(kt * 32));
#pragma unroll
                for (int nt = 0; nt < 4; ++nt)
                    mma16(acc0[mt][nt], a, w0[nt][kt]);
            }
        }

        // join: guards sBit(t-1) from warp0 AND h1(t-1) epi1 writes from all warps
        BAR_SYNC(1);

        // ---- epilogue0: h0' = tanh(acc0 + bias + onehot) -> h0[wr] ----
#pragma unroll
        for (int mt = 0; mt < 2; ++mt)
#pragma unroll
            for (int hh = 0; hh < 2; ++hh) {
                const int row = mt * 16 + g + hh * 8;
                const int bit = sBit[row];
                const float* cs = scTab + bit * 128;
#pragma unroll
                for (int nt = 0; nt < 4; ++nt) {
                    const int jc = 32 * w + nt * 8 + 2 * tq;
                    float v0 = acc0[mt][nt][hh * 2]     + cs[jc];
                    float v1 = acc0[mt][nt][hh * 2 + 1] + cs[jc + 1];
                    hcwm[row * HLD + 16 * w + nt * 4 + tq] =
                        pk_bf(tanh_fast(v0), tanh_fast(v1));
                }
            }

        // ========== L1a: acc1 = h1[rd] @ W_hh1^T (safe: post-BAR1) ==========
        float acc1[2][4][4];
#pragma unroll
        for (int mt = 0; mt < 2; ++mt)
#pragma unroll
            for (int nt = 0; nt < 4; ++nt)
#pragma unroll
                for (int i = 0; i < 4; ++i) acc1[mt][nt][i] = 0.f;

#pragma unroll
        for (int kt = 0; kt < 8; ++kt) {
            uint32_t b0q[4], b1q[4];
            ldmB(b0q, bAddr[0][1] + (uint32_t)(kt * 32));
            ldmB(b1q, bAddr[1][1] + (uint32_t)(kt * 32));
#pragma unroll
            for (int mt = 0; mt < 2; ++mt) {
                uint32_t a[4];
                ldmA(a, hb0 + rdoff + 256u + (uint32_t)(kt * 32)
                        + (uint32_t)(mt * 16 * HLD * 4));
                mma16(acc1[mt][0], a, b0q);
                mma16(acc1[mt][1], a, b0q + 2);
                mma16(acc1[mt][2], a, b1q);
                mma16(acc1[mt][3], a, b1q + 2);
            }
        }
        __syncthreads();   // h0'[wr] visible to all warps

        // ========== L1b: acc1 += h0'[wr] @ W_ih1^T (short post-sync path) ==========
#pragma unroll
        for (int kt = 0; kt < 8; ++kt) {
            uint32_t b0q[4], b1q[4];
            ldmB(b0q, bAddr[0][0] + (uint32_t)(kt * 32));
            ldmB(b1q, bAddr[1][0] + (uint32_t)(kt * 32));
#pragma unroll
            for (int mt = 0; mt < 2; ++mt) {
                uint32_t a[4];
                ldmA(a, hb0 + wroff + (uint32_t)(kt * 32)
                        + (uint32_t)(mt * 16 * HLD * 4));
                mma16(acc1[mt][0], a, b0q);
                mma16(acc1[mt][1], a, b0q + 2);
                mma16(acc1[mt][2], a, b1q);
                mma16(acc1[mt][3], a, b1q + 2);
            }
        }

        // ---- epilogue1: h1' = tanh(acc1 + b1) -> h1[wr]; dense partials ----
#pragma unroll
        for (int mt = 0; mt < 2; ++mt)
#pragma unroll
            for (int hh = 0; hh < 2; ++hh) {
                const int row = mt * 16 + g + hh * 8;
                float q0 = 0.f, q1 = 0.f;
#pragma unroll
                for (int nt = 0; nt < 4; ++nt) {
                    const int jc = 32 * w + nt * 8 + 2 * tq;
                    float v0 = acc1[mt][nt][hh * 2]     + sB1v[jc];
                    float v1 = acc1[mt][nt][hh * 2 + 1] + sB1v[jc + 1];
                    float t0 = tanh_fast(v0), t1 = tanh_fast(v1);
                    q0 = fmaf(t0, sWd[jc], fmaf(t1, sWd[jc + 1], q0));
                    q1 = fmaf(t0, sWd[128 + jc], fmaf(t1, sWd[128 + jc + 1], q1));
                    hcwm[row * HLD + 64 + 16 * w + nt * 4 + tq] = pk_bf(t0, t1);
                }
                q0 += __shfl_xor_sync(0xffffffffu, q0, 1);
                q0 += __shfl_xor_sync(0xffffffffu, q0, 2);
                q1 += __shfl_xor_sync(0xffffffffu, q1, 1);
                q1 += __shfl_xor_sync(0xffffffffu, q1, 2);
                if (tq == 0) {
                    sPart[w * 64 + row]      = q0;
                    sPart[w * 64 + 32 + row] = q1;
                }
            }

        // ---- dense tail: only warp 0 blocks; warps 1-3 run ahead into L0(t+1) ----
        if (w == 0) {
            BAR_SYNC(2);        // wait for all sPart writes
            float L0 = bd0, L1 = bd1;
#pragma unroll
            for (int ww = 0; ww < 4; ++ww) {
                L0 += sPart[ww * 64 + lane];
                L1 += sPart[ww * 64 + 32 + lane];
            }
            float m = fmaxf(L0, L1);
            float lse = m + __logf(__expf(L0 - m) + __expf(L1 - m));
            int bit = (s1 > 0.5f) ? 1 : 0;
            lp += (bit ? L1 : L0) - lse;
            sBit[lane] = bit;
        } else {
            BAR_ARRIVE(2);
        }
    }

    if (tid < BC) out[gRow] = lp;
}

extern "C" void kernel_launch(void* const* d_in, const int* in_sizes, int n_in,
                              void* d_out, int out_size) {
    (void)in_sizes; (void)n_in; (void)out_size;
    cudaFuncSetAttribute(rnn_bf16f_kernel,
                         cudaFuncAttributeMaxDynamicSharedMemorySize, SMEM_BYTES);
    rnn_bf16f_kernel<<<BATCH / BC, NT, SMEM_BYTES>>>(
        (const float*)d_in[0],
        (const float*)d_in[1], (const float*)d_in[2],
        (const float*)d_in[3], (const float*)d_in[4],
        (const float*)d_in[5], (const float*)d_in[6],
        (const float*)d_in[7], (const float*)d_in[8],
        (const float*)d_in[9], (const float*)d_in[10],
        (float*)d_out);
}